// round 15
// baseline (speedup 1.0000x reference)
#include <cuda_runtime.h>
#include <cuda_bf16.h>
#include <cstdint>

// ============================================================================
// Problem constants (TOKENS=8192, IN_F=4096, OUT_F=11008)
// ============================================================================
#define INF      4096
#define TOK_MAX  8192
#define OUT_MAX  11008

// True only on virtual archs admitting tcgen05 (sm_103a / family-specific).
#if defined(__CUDA_ARCH__) && (defined(__CUDA_ARCH_FEAT_SM103_ALL) || \
    defined(__CUDA_ARCH_SPECIFIC__) || defined(__CUDA_ARCH_FAMILY_SPECIFIC__))
#define HAS_TC 1
#else
#define HAS_TC 0
#endif

// ---------------- fallback (mma.sync s8) tiling ----------------
#define BM       128
#define BN       128
#define BK       64
#define STAGES   4
#define KTILES   (INF / BK)               // 64
#define STAGE_BYTES (BM * BK + BN * BK)   // 16384
#define SMEM_TOTAL  (STAGES * STAGE_BYTES) // 65536

// ---------------- tcgen05 cg2 bf16 tiling (N=512 per pair) ----------------
#define TCBKE    64                        // K elements per ktile (128B rows)
#define TCKT     (INF / TCBKE)             // 64
#define PANEL    16384                     // 128 rows x 128B, SW128-swizzled
#define TCSTAGES 4
#define TC_STG(s) (1024 + (s) * 3 * PANEL)   // A | B0 | B1
#define TC_SMEM   (1024 + TCSTAGES * 3 * PANEL)   // 197632
// mbarrier offsets (per CTA) — per-(stage,half) granularity
#define MB_F(s, h) (128 + 8 * (2 * (s) + (h)))   // FULL:  count=2 (both CTAs)
#define MB_E(s, h) (320 + 8 * (2 * (s) + (h)))   // EMPTY: count=1 (mma commit)
#define MB_DONE    448                           // flips exactly once

// ============================================================================
// Device scratch (static globals — no runtime allocation allowed)
// ============================================================================
__device__ __align__(16) int8_t g_Aq[(size_t)TOK_MAX * INF];       // fb path
__device__ __align__(16) int8_t g_Wq[(size_t)OUT_MAX * INF];       // fb path
// tc path: pre-swizzled panels. A: [64 mtiles][64 kt][16KB]; B: [86 nsub][64 kt][16KB]
__device__ __align__(1024) __nv_bfloat16 g_Aqh[(size_t)TOK_MAX * INF];
__device__ __align__(1024) __nv_bfloat16 g_Wqh[(size_t)OUT_MAX * INF];
__device__ float  g_ascale[TOK_MAX];
__device__ float  g_azp[TOK_MAX];
__device__ int    g_aqsum[TOK_MAX];
__device__ int    g_wsum[OUT_MAX];
__device__ int    g_wfmt;   // 1 = weights delivered as int32, 0 = raw int8

// ============================================================================
// Portable PTX helpers
// ============================================================================
__device__ __forceinline__ uint32_t smem_to_u32(const void* p) {
    uint32_t a;
    asm("{ .reg .u64 tmp; cvta.to.shared.u64 tmp, %1; cvt.u32.u64 %0, tmp; }"
        : "=r"(a) : "l"(p));
    return a;
}

#define CP_ASYNC16(smem_u32, gptr) \
    asm volatile("cp.async.cg.shared.global [%0], [%1], 16;" \
        :: "r"(smem_u32), "l"(gptr) : "memory")
#define CP_COMMIT() asm volatile("cp.async.commit_group;" ::: "memory")
#define CP_WAIT(n)  asm volatile("cp.async.wait_group %0;" :: "n"(n) : "memory")

#define NAMED_BAR(id, cnt) \
    asm volatile("bar.sync %0, %1;" :: "r"(id), "r"(cnt) : "memory")

__device__ __forceinline__ void ldmatrix_x4(uint32_t& r0, uint32_t& r1,
                                            uint32_t& r2, uint32_t& r3,
                                            uint32_t addr) {
    asm volatile("ldmatrix.sync.aligned.m8n8.x4.shared.b16 {%0,%1,%2,%3}, [%4];"
        : "=r"(r0), "=r"(r1), "=r"(r2), "=r"(r3) : "r"(addr));
}

__device__ __forceinline__ void mma_s8(int* c, const uint32_t* a,
                                       uint32_t b0, uint32_t b1) {
    asm volatile(
        "mma.sync.aligned.m16n8k32.row.col.s32.s8.s8.s32 "
        "{%0,%1,%2,%3}, {%4,%5,%6,%7}, {%8,%9}, {%0,%1,%2,%3};"
        : "+r"(c[0]), "+r"(c[1]), "+r"(c[2]), "+r"(c[3])
        : "r"(a[0]), "r"(a[1]), "r"(a[2]), "r"(a[3]), "r"(b0), "r"(b1));
}

#define SWZ_CHUNK(row, ch) ((ch) ^ (((row) >> 1) & 3))   // 64B-row tiles (fb)
#define SWZ128(o) ((o) ^ (((o) >> 3) & 0x70))            // SW128 (tc panels)

#define MBARRIER_INIT(mbar, count) \
    asm volatile("mbarrier.init.shared.b64 [%0], %1;" \
        :: "r"((uint32_t)(mbar)), "r"((uint32_t)(count)) : "memory")

// Arrive on the mbarrier at the same SMEM offset in cluster CTA target_rank.
#define MBARRIER_ARRIVE_CLUSTER(local_mbar_addr, target_rank) \
    asm volatile( \
        "{\n\t" \
        ".reg .b32 remAddr32;\n\t" \
        "mapa.shared::cluster.u32 remAddr32, %0, %1;\n\t" \
        "mbarrier.arrive.shared::cluster.b64 _, [remAddr32];\n\t" \
        "}" \
        :: "r"((uint32_t)(local_mbar_addr)), "r"((uint32_t)(target_rank)) \
        : "memory")

#define MBARRIER_WAIT_PARITY_SC(SCOPE, mbar_smem_addr, phase_parity) do { \
    uint32_t _mbar = (uint32_t)(mbar_smem_addr); \
    uint32_t _parity = (uint32_t)(phase_parity); \
    uint32_t _done; \
    asm volatile( \
        "{\n\t" \
        ".reg .pred p;\n\t" \
        "mbarrier.try_wait.parity.acquire." SCOPE ".shared::cta.b64 p, [%1], %2;\n\t" \
        "selp.b32 %0, 1, 0, p;\n\t" \
        "}" \
        : "=r"(_done) : "r"(_mbar), "r"(_parity) : "memory"); \
    if (!_done) { \
        asm volatile( \
            "{\n\t" \
            ".reg .pred P1;\n\t" \
            "WAIT_LOOP_%=:\n\t" \
            "mbarrier.try_wait.parity.acquire." SCOPE ".shared::cta.b64 P1, [%0], %1, 0x989680;\n\t" \
            "@P1 bra.uni WAIT_DONE_%=;\n\t" \
            "bra.uni WAIT_LOOP_%=;\n\t" \
            "WAIT_DONE_%=:\n\t" \
            "}" \
            :: "r"(_mbar), "r"(_parity) : "memory"); \
    } \
} while(0)

#define MBARRIER_WAIT_PARITY(m, p)      MBARRIER_WAIT_PARITY_SC("cta", m, p)
#define MBARRIER_WAIT_PARITY_CLUS(m, p) MBARRIER_WAIT_PARITY_SC("cluster", m, p)

#define CLUSTER_SYNC() do { \
    asm volatile("barrier.cluster.arrive.aligned;" ::: "memory"); \
    asm volatile("barrier.cluster.wait.aligned;" ::: "memory"); \
} while(0)

#define FENCE_PROXY_ASYNC() \
    asm volatile("fence.proxy.async.shared::cta;" ::: "memory")

// ---- tcgen05 cg2 macros (used only inside HAS_TC bodies) ----
#define TCGEN05_ALLOC_CG2(smem_result_addr, nCols) \
    asm volatile("tcgen05.alloc.cta_group::2.sync.aligned.shared::cta.b32 [%0], %1;" \
        :: "r"((uint32_t)(smem_result_addr)), "r"((uint32_t)(nCols)) : "memory")
#define TCGEN05_DEALLOC_CG2(tmem_addr, nCols) \
    asm volatile("tcgen05.dealloc.cta_group::2.sync.aligned.b32 %0, %1;" \
        :: "r"(tmem_addr), "r"((uint32_t)(nCols)))
#define TCGEN05_RELINQUISH_CG2() \
    asm volatile("tcgen05.relinquish_alloc_permit.cta_group::2.sync.aligned;")
#define TCGEN05_COMMIT_MC_CG2(mbar, mask) \
    asm volatile( \
        "tcgen05.commit.cta_group::2.mbarrier::arrive::one.shared::cluster.multicast::cluster.b64 [%0], %1;" \
        :: "r"((uint32_t)(mbar)), "h"((uint16_t)(mask)) : "memory")
#define TCGEN05_WAIT_LD() \
    asm volatile("tcgen05.wait::ld.sync.aligned;" ::: "memory")
#define TCGEN05_FENCE_AFTER() \
    asm volatile("tcgen05.fence::after_thread_sync;" ::: "memory")

#define TCGEN05_LD_32X32B_X32(r, tmem_addr) \
    asm volatile( \
        "tcgen05.ld.sync.aligned.32x32b.x32.b32 " \
        "{%0, %1, %2, %3, %4, %5, %6, %7, " \
        " %8, %9, %10, %11, %12, %13, %14, %15, " \
        " %16, %17, %18, %19, %20, %21, %22, %23, " \
        " %24, %25, %26, %27, %28, %29, %30, %31}, [%32];" \
        : "=r"((r)[0]),  "=r"((r)[1]),  "=r"((r)[2]),  "=r"((r)[3]), \
          "=r"((r)[4]),  "=r"((r)[5]),  "=r"((r)[6]),  "=r"((r)[7]), \
          "=r"((r)[8]),  "=r"((r)[9]),  "=r"((r)[10]), "=r"((r)[11]), \
          "=r"((r)[12]), "=r"((r)[13]), "=r"((r)[14]), "=r"((r)[15]), \
          "=r"((r)[16]), "=r"((r)[17]), "=r"((r)[18]), "=r"((r)[19]), \
          "=r"((r)[20]), "=r"((r)[21]), "=r"((r)[22]), "=r"((r)[23]), \
          "=r"((r)[24]), "=r"((r)[25]), "=r"((r)[26]), "=r"((r)[27]), \
          "=r"((r)[28]), "=r"((r)[29]), "=r"((r)[30]), "=r"((r)[31]) \
        : "r"(tmem_addr))

// SW128 K-major SMEM descriptor (matches working bf16 examples)
static constexpr uint64_t SMEM_DESC_BASE_SW128 =
    (uint64_t(2) << 61) | (uint64_t(1) << 46) | (uint64_t(64) << 32) | (uint64_t(1) << 16);
#define MAKE_SMEM_DESC(base_addr) \
    (SMEM_DESC_BASE_SW128 | ((uint64_t)((base_addr) >> 4) & 0x3FFF))

#if HAS_TC
// cg2 bf16 SS MMA (from test_2cta_mma_bf16.cu)
__device__ __forceinline__ void mma_bf16_ss_cg2(uint32_t d_tmem, uint64_t a_desc,
                                                uint64_t b_desc, uint32_t idesc,
                                                uint32_t en) {
    asm volatile(
        "{\n\t"
        ".reg .pred p;\n\t"
        "setp.ne.u32 p, %5, 0;\n\t"
        "tcgen05.mma.cta_group::2.kind::f16 [%0], %1, %2, %3, "
        "{%4, %4, %4, %4, %4, %4, %4, %4}, p;\n\t"
        "}"
        :: "r"(d_tmem), "l"(a_desc), "l"(b_desc), "r"(idesc), "r"(0u), "r"(en)
        : "memory");
}
#endif

// idesc kind::f16 cg2: dtype=F32, a/b=BF16, N=256 -> 32<<17, M=256 -> 16<<24
static constexpr uint32_t IDESC_CG2 =
    (1u << 4) | (1u << 7) | (1u << 10) | (32u << 17) | (16u << 24);

// ============================================================================
// Kernel 0a: probe weight delivery format
// ============================================================================
__global__ void wprobe_kernel(const int* __restrict__ W32) {
    __shared__ int ok;
    if (threadIdx.x == 0) ok = 1;
    __syncthreads();
    for (int i = threadIdx.x; i < 8192; i += 256) {
        int v = W32[i];
        if (v < -128 || v > 127) ok = 0;
    }
    __syncthreads();
    if (threadIdx.x == 0) g_wfmt = ok;
}

// ============================================================================
// Kernel 0b: repack weights + per-channel row sums.
// tc path: bf16 into SW128 panels [o>>7][kt][16KB]. fb path: linear int8.
// ============================================================================
__global__ void __launch_bounds__(256) wrepack_kernel(const void* __restrict__ Wraw) {
    const int o = blockIdx.x;
    int s = 0;
#pragma unroll
    for (int k = 0; k < 4; k++) {
        const int i = threadIdx.x + k * 256;   // group of 4 weights
        int w0, w1, w2, w3;
        if (g_wfmt) {
            int4 v = ((const int4*)((const int*)Wraw + (size_t)o * INF))[i];
            w0 = v.x; w1 = v.y; w2 = v.z; w3 = v.w;
        } else {
            int v = ((const int*)((const int8_t*)Wraw + (size_t)o * INF))[i];
            w0 = (int)(int8_t)(v);       w1 = (int)(int8_t)(v >> 8);
            w2 = (int)(int8_t)(v >> 16); w3 = (int)(int8_t)(v >> 24);
        }
        s += w0 + w1 + w2 + w3;
#if HAS_TC
        __nv_bfloat162 h0, h1;
        h0.x = __float2bfloat16_rn((float)w0); h0.y = __float2bfloat16_rn((float)w1);
        h1.x = __float2bfloat16_rn((float)w2); h1.y = __float2bfloat16_rn((float)w3);
        const int e = i * 4;                    // element index within row
        const int kt = e >> 6, r = o & 127;
        const uint32_t boff = (uint32_t)(r * 128 + (e & 63) * 2);
        char* dst = (char*)g_Wqh + ((size_t)((o >> 7) * TCKT + kt)) * PANEL
                    + SWZ128(boff);
        *(uint2*)dst = make_uint2(*(uint32_t*)&h0, *(uint32_t*)&h1);
#else
        unsigned packed = (w0 & 0xff) | ((w1 & 0xff) << 8) |
                          ((w2 & 0xff) << 16) | ((unsigned)(w3 & 0xff) << 24);
        ((unsigned*)(g_Wq + (size_t)o * INF))[i] = packed;
#endif
    }
#pragma unroll
    for (int off = 16; off; off >>= 1) s += __shfl_xor_sync(0xffffffffu, s, off);
    __shared__ int ss[8];
    if ((threadIdx.x & 31) == 0) ss[threadIdx.x >> 5] = s;
    __syncthreads();
    if (threadIdx.x == 0) {
        int tot = 0;
#pragma unroll
        for (int i = 0; i < 8; i++) tot += ss[i];
        g_wsum[o] = tot;
    }
}

// ============================================================================
// Kernel 1: per-token dynamic asymmetric int8 quant (torchao recipe)
// tc path writes bf16 SW128 panels [t>>7][kt][16KB].
// ============================================================================
__global__ void __launch_bounds__(256) quant_kernel(const float* __restrict__ x) {
    const int t = blockIdx.x;
    const float4* xr = (const float4*)(x + (size_t)t * INF);

    float4 v[4];
    float mn = 1e38f, mx = -1e38f;
#pragma unroll
    for (int k = 0; k < 4; k++) {
        v[k] = xr[threadIdx.x + k * 256];
        mn = fminf(mn, fminf(fminf(v[k].x, v[k].y), fminf(v[k].z, v[k].w)));
        mx = fmaxf(mx, fmaxf(fmaxf(v[k].x, v[k].y), fmaxf(v[k].z, v[k].w)));
    }
#pragma unroll
    for (int o = 16; o; o >>= 1) {
        mn = fminf(mn, __shfl_xor_sync(0xffffffffu, mn, o));
        mx = fmaxf(mx, __shfl_xor_sync(0xffffffffu, mx, o));
    }

    __shared__ float smn[8], smx[8], sparams[3];
    __shared__ int sqsum;
    const int wid = threadIdx.x >> 5, lid = threadIdx.x & 31;
    if (lid == 0) { smn[wid] = mn; smx[wid] = mx; }
    if (threadIdx.x == 0) sqsum = 0;
    __syncthreads();

    if (threadIdx.x == 0) {
        float rmn = smn[0], rmx = smx[0];
#pragma unroll
        for (int i = 1; i < 8; i++) { rmn = fminf(rmn, smn[i]); rmx = fmaxf(rmx, smx[i]); }
        float min_neg = fminf(rmn, 0.0f);
        float max_pos = fmaxf(rmx, 0.0f);
        float scale = __fdiv_rn(max_pos - min_neg, 255.0f);
        scale = fmaxf(scale, 1.1920928955078125e-07f);
        float dmin = __fdiv_rn(min_neg, scale);
        float dmax = __fdiv_rn(max_pos, scale);
        float zpf = (((-128.0f + dmin) + (127.0f + dmax)) > 0.0f)
                        ? (-128.0f - dmin) : (127.0f - dmax);
        zpf = fminf(fmaxf(rintf(zpf), -128.0f), 127.0f);
        sparams[0] = scale;
        sparams[1] = zpf;
        sparams[2] = __frcp_rn(scale);
    }
    __syncthreads();

    const float scale = sparams[0], zp = sparams[1], rcp = sparams[2];
    int qsum = 0;
#pragma unroll
    for (int k = 0; k < 4; k++) {
        float e4[4] = {v[k].x, v[k].y, v[k].z, v[k].w};
        int q[4];
#pragma unroll
        for (int j = 0; j < 4; j++) {
            float y0 = __fmul_rn(e4[j], rcp);
            float y = fmaf(fmaf(-scale, y0, e4[j]), rcp, y0);  // IEEE-div accurate
            float qf = fminf(fmaxf(rintf(y) + zp, -128.0f), 127.0f);
            q[j] = (int)qf;
            qsum += q[j];
        }
        const int i = threadIdx.x + k * 256;
#if HAS_TC
        __nv_bfloat162 h0, h1;
        h0.x = __float2bfloat16_rn((float)q[0]); h0.y = __float2bfloat16_rn((float)q[1]);
        h1.x = __float2bfloat16_rn((float)q[2]); h1.y = __float2bfloat16_rn((float)q[3]);
        const int e = i * 4;
        const int kt = e >> 6, r = t & 127;
        const uint32_t boff = (uint32_t)(r * 128 + (e & 63) * 2);
        char* dst = (char*)g_Aqh + ((size_t)((t >> 7) * TCKT + kt)) * PANEL
                    + SWZ128(boff);
        *(uint2*)dst = make_uint2(*(uint32_t*)&h0, *(uint32_t*)&h1);
#else
        unsigned packed = (q[0] & 0xff) | ((q[1] & 0xff) << 8) |
                          ((q[2] & 0xff) << 16) | ((unsigned)(q[3] & 0xff) << 24);
        ((int*)g_Aq)[(size_t)t * (INF / 4) + i] = (int)packed;
#endif
    }

#pragma unroll
    for (int o = 16; o; o >>= 1) qsum += __shfl_xor_sync(0xffffffffu, qsum, o);
    if (lid == 0) atomicAdd(&sqsum, qsum);
    __syncthreads();
    if (threadIdx.x == 0) {
        g_ascale[t] = scale;
        g_azp[t]    = zp;
        g_aqsum[t]  = sqsum;
    }
}

// ============================================================================
// Kernel 2a: cg2 tcgen05 bf16 GEMM, N=512 per pair — HALF-STAGE pipeline:
// each 48KB stage splits into K-lo (dispatch j=0,1) and K-hi (j=2,3)
// half-groups with independent FULL/EMPTY barriers, halving the latency
// exposure per dependency edge. 256 threads: 192 loaders + lean MMA thread.
// ============================================================================
__global__ void __launch_bounds__(256, 1) __cluster_dims__(2, 1, 1)
gemm_tc(float* __restrict__ out,
        const float* __restrict__ scales, const float* __restrict__ zeros,
        int OUTF) {
#if HAS_TC
    extern __shared__ char smem[];
    const uint32_t sb = smem_to_u32(smem);
    const int tid = threadIdx.x;
    const int wid = tid >> 5;
    uint32_t rank;
    asm("mov.u32 %0, %%cluster_ctarank;" : "=r"(rank));
    const int m0 = blockIdx.x * 128;          // this CTA's 128 token rows
    const int n0 = blockIdx.y * 512;          // pair's n-tile base
    const int nh = (n0 + 512 <= OUTF) ? 2 : 1; // halves present in this tile

    if (wid == 0) TCGEN05_ALLOC_CG2(sb, 512);
    if (tid == 0) {
#pragma unroll
        for (int s = 0; s < TCSTAGES; s++)
#pragma unroll
            for (int h = 0; h < 2; h++) {
                MBARRIER_INIT(sb + MB_F(s, h), 2);
                MBARRIER_INIT(sb + MB_E(s, h), 1);
            }
        MBARRIER_INIT(sb + MB_DONE, 1);
    }
    __syncthreads();
    uint32_t tmem;
    asm volatile("ld.shared.b32 %0, [%1];" : "=r"(tmem) : "r"(sb));
    if (wid == 0) TCGEN05_RELINQUISH_CG2();
    CLUSTER_SYNC();   // mbarriers visible cluster-wide before any remote arrive

    if (tid >= 64) {
        // ===== loaders: 192 threads, 64 per panel, half-group granularity ===
        const int lt = tid - 64;        // 0..191
        const int p  = lt >> 6;         // panel 0..2
        const int ln = lt & 63;
        const char* src_base;
        if (p == 0)
            src_base = (const char*)g_Aqh + (size_t)blockIdx.x * TCKT * PANEL;
        else if (p == 1)
            src_base = (const char*)g_Wqh +
                       (size_t)(blockIdx.y * 4 + rank) * TCKT * PANEL;
        else
            src_base = (const char*)g_Wqh +
                       (size_t)(blockIdx.y * 4 + 2 + rank) * TCKT * PANEL;
        const bool active = (p < 1 + nh);
        const uint32_t dst_p = sb + 1024 + (uint32_t)p * PANEL;
        const int r0 = ln * 2;          // this thread's 2 rows

        // issue half h of stage s/ktile kt: rows r0,r0+1, pre-swizzled chunks
        auto issue_half = [&](int s, int kt, int h) {
            if (active) {
                const uint32_t dst = dst_p + (uint32_t)s * (3 * PANEL);
                const char* src = src_base + (size_t)kt * PANEL;
#pragma unroll
                for (int rr = 0; rr < 2; rr++) {
                    const int r = r0 + rr;
                    const uint32_t rowoff = (uint32_t)r * 128;
                    const uint32_t x = (uint32_t)(r & 7) << 4;
#pragma unroll
                    for (int c = 0; c < 4; c++) {
                        const uint32_t off =
                            rowoff + ((((uint32_t)(c + 4 * h)) << 4) ^ x);
                        CP_ASYNC16(dst + off, src + off);
                    }
                }
            }
        };

        // half-group index g = 2*kt + h; groups committed individually
        issue_half(0, 0, 0); CP_COMMIT();   // g=0
        issue_half(0, 0, 1); CP_COMMIT();   // g=1
        const int G = 2 * TCKT;
        for (int g = 2; g < G; g++) {
            const int kt = g >> 1, h = g & 1, s = kt & 3;
            if (kt >= 4)   // buffer half reused: MMA(kt-4) half h retired
                MBARRIER_WAIT_PARITY(sb + MB_E(s, h), ((kt - 4) >> 2) & 1);
            issue_half(s, kt, h);
            CP_COMMIT();
            CP_WAIT(2);              // group g-2 drained (this thread)
            NAMED_BAR(1, 192);       // all loaders drained group g-2
            if (lt == 0) {
                FENCE_PROXY_ASYNC();
                const int gp = g - 2;
                MBARRIER_ARRIVE_CLUSTER(sb + MB_F((gp >> 1) & 3, gp & 1), 0);
            }
        }
        CP_WAIT(1);                  // group G-2 drained
        NAMED_BAR(1, 192);
        if (lt == 0) {
            FENCE_PROXY_ASYNC();
            MBARRIER_ARRIVE_CLUSTER(sb + MB_F(((G - 2) >> 1) & 3, 0), 0);
        }
        CP_WAIT(0);                  // group G-1 drained
        NAMED_BAR(1, 192);
        if (lt == 0) {
            FENCE_PROXY_ASYNC();
            MBARRIER_ARRIVE_CLUSTER(sb + MB_F(((G - 1) >> 1) & 3, 1), 0);
        }
    } else if (tid == 0 && rank == 0) {
        // =================== lean MMA issuer (pair leader) ==================
        uint64_t adv[4], bd0v[4], bd1v[4];
#pragma unroll
        for (int s = 0; s < 4; s++) {
            adv[s]  = MAKE_SMEM_DESC(sb + TC_STG(s));
            bd0v[s] = MAKE_SMEM_DESC(sb + TC_STG(s) + PANEL);
            bd1v[s] = MAKE_SMEM_DESC(sb + TC_STG(s) + 2 * PANEL);
        }
        for (int kt = 0; kt < TCKT; kt++) {
            const int s = kt & 3;
            const uint32_t par = (kt >> 2) & 1;
            // ---- K-lo half: dispatches j=0,1 ----
            MBARRIER_WAIT_PARITY_CLUS(sb + MB_F(s, 0), par);
#pragma unroll
            for (int j = 0; j < 2; j++) {
                mma_bf16_ss_cg2(tmem, adv[s] + j * 2, bd0v[s] + j * 2,
                                IDESC_CG2, (uint32_t)((kt | j) != 0));
                if (nh == 2)
                    mma_bf16_ss_cg2(tmem + 256, adv[s] + j * 2, bd1v[s] + j * 2,
                                    IDESC_CG2, (uint32_t)((kt | j) != 0));
            }
            TCGEN05_COMMIT_MC_CG2(sb + MB_E(s, 0), 0x3);
            // ---- K-hi half: dispatches j=2,3 ----
            MBARRIER_WAIT_PARITY_CLUS(sb + MB_F(s, 1), par);
#pragma unroll
            for (int j = 2; j < 4; j++) {
                mma_bf16_ss_cg2(tmem, adv[s] + j * 2, bd0v[s] + j * 2,
                                IDESC_CG2, 1u);
                if (nh == 2)
                    mma_bf16_ss_cg2(tmem + 256, adv[s] + j * 2, bd1v[s] + j * 2,
                                    IDESC_CG2, 1u);
            }
            TCGEN05_COMMIT_MC_CG2(sb + MB_E(s, 1), 0x3);
        }
        TCGEN05_COMMIT_MC_CG2(sb + MB_DONE, 0x3);  // single-flip completion
    }

    // everyone (both CTAs): wait the once-only DONE flip
    MBARRIER_WAIT_PARITY_CLUS(sb + MB_DONE, 0);
    TCGEN05_FENCE_AFTER();

    // ---- epilogue: dequant f32 accumulators; smem transpose for coalesced IO
    // TMEM reads on warps 0..3 (lane->row mapping); copy-out uses all 256.
    const int t = m0 + tid;              // valid only for tid < 128
    float s_t = 0.f, zp = 0.f, ct = 0.f;
    if (tid < 128) {
        s_t = g_ascale[t];
        zp  = g_azp[t];
        ct  = (float)g_aqsum[t] - (float)INF * zp;
    }
    float* xp = (float*)(smem + 1024);   // 128 rows x 68 floats (reuses stages)

    const int nch = nh * 4;
    for (int ch = 0; ch < nch; ch++) {
        uint32_t r[64];
        if (tid < 128) {
            TCGEN05_LD_32X32B_X32(r, tmem + ch * 64);
            TCGEN05_LD_32X32B_X32(r + 32, tmem + ch * 64 + 32);
            TCGEN05_WAIT_LD();
        }
        const int cb = n0 + ch * 64;
        __syncthreads();   // previous iteration's xp reads complete
        if (tid < 128) {
#pragma unroll
            for (int c = 0; c < 64; c += 4) {
                float4 v;
                v.x = s_t * __ldg(scales + cb + c + 0) *
                      (__uint_as_float(r[c + 0]) - zp * (float)g_wsum[cb + c + 0] - __ldg(zeros + cb + c + 0) * ct);
                v.y = s_t * __ldg(scales + cb + c + 1) *
                      (__uint_as_float(r[c + 1]) - zp * (float)g_wsum[cb + c + 1] - __ldg(zeros + cb + c + 1) * ct);
                v.z = s_t * __ldg(scales + cb + c + 2) *
                      (__uint_as_float(r[c + 2]) - zp * (float)g_wsum[cb + c + 2] - __ldg(zeros + cb + c + 2) * ct);
                v.w = s_t * __ldg(scales + cb + c + 3) *
                      (__uint_as_float(r[c + 3]) - zp * (float)g_wsum[cb + c + 3] - __ldg(zeros + cb + c + 3) * ct);
                *(float4*)(xp + tid * 68 + c) = v;
            }
        }
        __syncthreads();
#pragma unroll
        for (int it = 0; it < 8; it++) {      // 2048 float4 over 256 threads
            int idx = it * 256 + tid;
            int row = idx >> 4, q = idx & 15;
            float4 v = *(const float4*)(xp + row * 68 + q * 4);
            *(float4*)(out + (size_t)(m0 + row) * OUTF + cb + q * 4) = v;
        }
    }

    __syncthreads();
    CLUSTER_SYNC();
    if (wid == 0) TCGEN05_DEALLOC_CG2(tmem, 512);
    CLUSTER_SYNC();
#endif  // HAS_TC
}

// ============================================================================
// Kernel 2b: fallback mma.sync s8 GEMM — non-'a' pass only
// ============================================================================
__global__ void __launch_bounds__(256, 2)
gemm_fb(float* __restrict__ out,
        const float* __restrict__ scales, const float* __restrict__ zeros,
        int OUTF) {
#if !HAS_TC
    extern __shared__ char smem[];
    const uint32_t sb = smem_to_u32(smem);
    const int tid  = threadIdx.x;
    const int lane = tid & 31;
    const int wid  = tid >> 5;
    const int warp_m = wid & 1;
    const int warp_n = wid >> 1;
    const int m0 = blockIdx.x * BM;
    const int n0 = blockIdx.y * BN;

    const int8_t* Abase = g_Aq + (size_t)m0 * INF;
    const int8_t* Bbase = g_Wq + (size_t)n0 * INF;

    auto load_stage = [&](int s, int kt) {
        const uint32_t st = sb + s * STAGE_BYTES;
        const int8_t* ga = Abase + kt * BK;
        const int8_t* gb = Bbase + kt * BK;
#pragma unroll
        for (int i = 0; i < 2; i++) {
            int idx = i * 256 + tid;
            int row = idx >> 2, ch = idx & 3;
            CP_ASYNC16(st + row * 64 + SWZ_CHUNK(row, ch) * 16,
                       ga + (size_t)row * INF + ch * 16);
        }
#pragma unroll
        for (int i = 0; i < 2; i++) {
            int idx = i * 256 + tid;
            int row = idx >> 2, ch = idx & 3;
            CP_ASYNC16(st + BM * BK + row * 64 + SWZ_CHUNK(row, ch) * 16,
                       gb + (size_t)row * INF + ch * 16);
        }
    };

    int acc[4][4][4];
#pragma unroll
    for (int i = 0; i < 4; i++)
#pragma unroll
        for (int j = 0; j < 4; j++)
#pragma unroll
            for (int k = 0; k < 4; k++) acc[i][j][k] = 0;

    const uint32_t key = ((lane & 15) >> 1) & 3;
    const int hi = lane >> 4;
    const uint32_t a_row = (uint32_t)(warp_m * 64 + (lane & 15)) * 64;
    const uint32_t b_row = (uint32_t)(warp_n * 32 + (lane & 15)) * 64;

#pragma unroll
    for (int s = 0; s < STAGES - 1; s++) { load_stage(s, s); CP_COMMIT(); }

    for (int kt = 0; kt < KTILES; kt++) {
        const int ns = kt + STAGES - 1;
        if (ns < KTILES) load_stage(ns & (STAGES - 1), ns);
        CP_COMMIT();
        CP_WAIT(STAGES - 1);
        __syncthreads();

        const uint32_t sA = sb + (kt & (STAGES - 1)) * STAGE_BYTES;
        const uint32_t sB = sA + BM * BK;
#pragma unroll
        for (int ks = 0; ks < 2; ks++) {
            const uint32_t choff = (uint32_t)(((ks << 1) | hi) ^ key) << 4;
            uint32_t a[4][4];
#pragma unroll
            for (int mf = 0; mf < 4; mf++)
                ldmatrix_x4(a[mf][0], a[mf][1], a[mf][2], a[mf][3],
                            sA + a_row + mf * 1024 + choff);
            uint32_t b0[4], b1[4];
#pragma unroll
            for (int p = 0; p < 2; p++)
                ldmatrix_x4(b0[2 * p], b0[2 * p + 1], b1[2 * p], b1[2 * p + 1],
                            sB + b_row + p * 1024 + choff);
#pragma unroll
            for (int mf = 0; mf < 4; mf++)
#pragma unroll
                for (int nf = 0; nf < 4; nf++)
                    mma_s8(acc[mf][nf], a[mf], b0[nf], b1[nf]);
        }
        __syncthreads();
    }

    float s_t[8], zp_t[8], ct_t[8];
#pragma unroll
    for (int mf = 0; mf < 4; mf++)
#pragma unroll
        for (int h = 0; h < 2; h++) {
            int r = m0 + warp_m * 64 + mf * 16 + (lane >> 2) + 8 * h;
            float s = g_ascale[r], z = g_azp[r];
            s_t[mf * 2 + h] = s;
            zp_t[mf * 2 + h] = z;
            ct_t[mf * 2 + h] = (float)g_aqsum[r] - (float)INF * z;
        }

#pragma unroll
    for (int nf = 0; nf < 4; nf++) {
        const int c0 = n0 + warp_n * 32 + nf * 8 + (lane & 3) * 2;
        const float sc0 = __ldg(scales + c0), sc1 = __ldg(scales + c0 + 1);
        const float z0  = __ldg(zeros + c0),  z1  = __ldg(zeros + c0 + 1);
        const float w0  = (float)g_wsum[c0],  w1  = (float)g_wsum[c0 + 1];
#pragma unroll
        for (int mf = 0; mf < 4; mf++)
#pragma unroll
            for (int h = 0; h < 2; h++) {
                const int r = m0 + warp_m * 64 + mf * 16 + (lane >> 2) + 8 * h;
                const float s = s_t[mf * 2 + h], zp = zp_t[mf * 2 + h],
                            ct = ct_t[mf * 2 + h];
                float2 v;
                v.x = s * sc0 * ((float)acc[mf][nf][h * 2 + 0] - zp * w0 - z0 * ct);
                v.y = s * sc1 * ((float)acc[mf][nf][h * 2 + 1] - zp * w1 - z1 * ct);
                *(float2*)(out + (size_t)r * OUTF + c0) = v;
            }
    }
#endif  // !HAS_TC
}

// ============================================================================
// Launcher — both GEMMs launched; exactly one is non-empty in the loaded SASS.
// ============================================================================
extern "C" void kernel_launch(void* const* d_in, const int* in_sizes, int n_in,
                              void* d_out, int out_size) {
    (void)n_in; (void)out_size;
    const float* x      = (const float*)d_in[0];
    const void*  w      = d_in[1];
    const float* scales = (const float*)d_in[2];
    const float* zeros  = (const float*)d_in[3];
    float* out = (float*)d_out;

    const int tokens = in_sizes[0] / INF;
    const int outf   = in_sizes[2];

    wprobe_kernel<<<1, 256>>>((const int*)w);
    wrepack_kernel<<<outf, 256>>>(w);
    quant_kernel<<<tokens, 256>>>(x);

    cudaFuncSetAttribute(gemm_tc,
                         cudaFuncAttributeMaxDynamicSharedMemorySize, TC_SMEM);
    cudaFuncSetAttribute(gemm_fb,
                         cudaFuncAttributeMaxDynamicSharedMemorySize, SMEM_TOTAL);

    // tc grid: x = 64 m-subtiles (cluster pairs adjacent x), y = n-tiles of 512
    gemm_tc<<<dim3(tokens / 128, (outf + 511) / 512), 256, TC_SMEM>>>(
        out, scales, zeros, outf);
    gemm_fb<<<dim3(tokens / BM, outf / BN), 256, SMEM_TOTAL>>>(
        out, scales, zeros, outf);
}

// round 17
// speedup vs baseline: 2.2525x; 2.2525x over previous
#include <cuda_runtime.h>
#include <cuda_bf16.h>
#include <cstdint>

// ============================================================================
// Problem constants (TOKENS=8192, IN_F=4096, OUT_F=11008)
// ============================================================================
#define INF      4096
#define TOK_MAX  8192
#define OUT_MAX  11008

// True only on virtual archs admitting tcgen05 (sm_103a / family-specific).
#if defined(__CUDA_ARCH__) && (defined(__CUDA_ARCH_FEAT_SM103_ALL) || \
    defined(__CUDA_ARCH_SPECIFIC__) || defined(__CUDA_ARCH_FAMILY_SPECIFIC__))
#define HAS_TC 1
#else
#define HAS_TC 0
#endif

// ---------------- fallback (mma.sync s8) tiling ----------------
#define BM       128
#define BN       128
#define BK       64
#define STAGES   4
#define KTILES   (INF / BK)               // 64
#define STAGE_BYTES (BM * BK + BN * BK)   // 16384
#define SMEM_TOTAL  (STAGES * STAGE_BYTES) // 65536

// ---------------- tcgen05 cg2 bf16 tiling (pair = 256 x 256) --------------
// 2 CTAs per SM (occupancy 2) to overlap pipeline latency. TMEM 256 cols/CTA.
#define TCBKE    64                        // K elements per ktile (128B rows)
#define TCKT     (INF / TCBKE)             // 64
#define PANEL    16384                     // 128 rows x 128B, SW128-swizzled
#define TCSTAGES 3
#define TC_STG(s) (1024 + (s) * 2 * PANEL)        // A | B (split half)
#define TC_SMEM   (1024 + TCSTAGES * 2 * PANEL)   // 99328 -> 2 CTAs/SM
// mbarrier offsets (per CTA)
#define MB_FULL(s)  (128 + 8 * (s))   // on rank0: both CTAs arrive, count=2
#define MB_EMPTY(s) (192 + 8 * (s))   // MMA-done (multicast commit), count=1
#define MB_DONE     256               // flips exactly once: all MMAs retired

// ============================================================================
// Device scratch (static globals — no runtime allocation allowed)
// ============================================================================
__device__ __align__(16) int8_t g_Aq[(size_t)TOK_MAX * INF];       // fb path
__device__ __align__(16) int8_t g_Wq[(size_t)OUT_MAX * INF];       // fb path
// tc path: pre-swizzled panels. A: [64 mtiles][64 kt][16KB]; B: [86 nsub][64 kt][16KB]
__device__ __align__(1024) __nv_bfloat16 g_Aqh[(size_t)TOK_MAX * INF];
__device__ __align__(1024) __nv_bfloat16 g_Wqh[(size_t)OUT_MAX * INF];
__device__ float  g_ascale[TOK_MAX];
__device__ float  g_azp[TOK_MAX];
__device__ int    g_aqsum[TOK_MAX];
__device__ int    g_wsum[OUT_MAX];
__device__ int    g_wfmt;   // 1 = weights delivered as int32, 0 = raw int8

// ============================================================================
// Portable PTX helpers
// ============================================================================
__device__ __forceinline__ uint32_t smem_to_u32(const void* p) {
    uint32_t a;
    asm("{ .reg .u64 tmp; cvta.to.shared.u64 tmp, %1; cvt.u32.u64 %0, tmp; }"
        : "=r"(a) : "l"(p));
    return a;
}

#define CP_ASYNC16(smem_u32, gptr) \
    asm volatile("cp.async.cg.shared.global [%0], [%1], 16;" \
        :: "r"(smem_u32), "l"(gptr) : "memory")
#define CP_COMMIT() asm volatile("cp.async.commit_group;" ::: "memory")
#define CP_WAIT(n)  asm volatile("cp.async.wait_group %0;" :: "n"(n) : "memory")

__device__ __forceinline__ void ldmatrix_x4(uint32_t& r0, uint32_t& r1,
                                            uint32_t& r2, uint32_t& r3,
                                            uint32_t addr) {
    asm volatile("ldmatrix.sync.aligned.m8n8.x4.shared.b16 {%0,%1,%2,%3}, [%4];"
        : "=r"(r0), "=r"(r1), "=r"(r2), "=r"(r3) : "r"(addr));
}

__device__ __forceinline__ void mma_s8(int* c, const uint32_t* a,
                                       uint32_t b0, uint32_t b1) {
    asm volatile(
        "mma.sync.aligned.m16n8k32.row.col.s32.s8.s8.s32 "
        "{%0,%1,%2,%3}, {%4,%5,%6,%7}, {%8,%9}, {%0,%1,%2,%3};"
        : "+r"(c[0]), "+r"(c[1]), "+r"(c[2]), "+r"(c[3])
        : "r"(a[0]), "r"(a[1]), "r"(a[2]), "r"(a[3]), "r"(b0), "r"(b1));
}

#define SWZ_CHUNK(row, ch) ((ch) ^ (((row) >> 1) & 3))   // 64B-row tiles (fb)
#define SWZ128(o) ((o) ^ (((o) >> 3) & 0x70))            // SW128 (tc panels)

#define MBARRIER_INIT(mbar, count) \
    asm volatile("mbarrier.init.shared.b64 [%0], %1;" \
        :: "r"((uint32_t)(mbar)), "r"((uint32_t)(count)) : "memory")

// Arrive on the mbarrier at the same SMEM offset in cluster CTA target_rank.
#define MBARRIER_ARRIVE_CLUSTER(local_mbar_addr, target_rank) \
    asm volatile( \
        "{\n\t" \
        ".reg .b32 remAddr32;\n\t" \
        "mapa.shared::cluster.u32 remAddr32, %0, %1;\n\t" \
        "mbarrier.arrive.shared::cluster.b64 _, [remAddr32];\n\t" \
        "}" \
        :: "r"((uint32_t)(local_mbar_addr)), "r"((uint32_t)(target_rank)) \
        : "memory")

#define MBARRIER_WAIT_PARITY_SC(SCOPE, mbar_smem_addr, phase_parity) do { \
    uint32_t _mbar = (uint32_t)(mbar_smem_addr); \
    uint32_t _parity = (uint32_t)(phase_parity); \
    uint32_t _done; \
    asm volatile( \
        "{\n\t" \
        ".reg .pred p;\n\t" \
        "mbarrier.try_wait.parity.acquire." SCOPE ".shared::cta.b64 p, [%1], %2;\n\t" \
        "selp.b32 %0, 1, 0, p;\n\t" \
        "}" \
        : "=r"(_done) : "r"(_mbar), "r"(_parity) : "memory"); \
    if (!_done) { \
        asm volatile( \
            "{\n\t" \
            ".reg .pred P1;\n\t" \
            "WAIT_LOOP_%=:\n\t" \
            "mbarrier.try_wait.parity.acquire." SCOPE ".shared::cta.b64 P1, [%0], %1, 0x989680;\n\t" \
            "@P1 bra.uni WAIT_DONE_%=;\n\t" \
            "bra.uni WAIT_LOOP_%=;\n\t" \
            "WAIT_DONE_%=:\n\t" \
            "}" \
            :: "r"(_mbar), "r"(_parity) : "memory"); \
    } \
} while(0)

#define MBARRIER_WAIT_PARITY(m, p)      MBARRIER_WAIT_PARITY_SC("cta", m, p)
#define MBARRIER_WAIT_PARITY_CLUS(m, p) MBARRIER_WAIT_PARITY_SC("cluster", m, p)

#define CLUSTER_SYNC() do { \
    asm volatile("barrier.cluster.arrive.aligned;" ::: "memory"); \
    asm volatile("barrier.cluster.wait.aligned;" ::: "memory"); \
} while(0)

#define FENCE_PROXY_ASYNC() \
    asm volatile("fence.proxy.async.shared::cta;" ::: "memory")

// ---- tcgen05 cg2 macros (used only inside HAS_TC bodies) ----
#define TCGEN05_ALLOC_CG2(smem_result_addr, nCols) \
    asm volatile("tcgen05.alloc.cta_group::2.sync.aligned.shared::cta.b32 [%0], %1;" \
        :: "r"((uint32_t)(smem_result_addr)), "r"((uint32_t)(nCols)) : "memory")
#define TCGEN05_DEALLOC_CG2(tmem_addr, nCols) \
    asm volatile("tcgen05.dealloc.cta_group::2.sync.aligned.b32 %0, %1;" \
        :: "r"(tmem_addr), "r"((uint32_t)(nCols)))
#define TCGEN05_RELINQUISH_CG2() \
    asm volatile("tcgen05.relinquish_alloc_permit.cta_group::2.sync.aligned;")
#define TCGEN05_COMMIT_MC_CG2(mbar, mask) \
    asm volatile( \
        "tcgen05.commit.cta_group::2.mbarrier::arrive::one.shared::cluster.multicast::cluster.b64 [%0], %1;" \
        :: "r"((uint32_t)(mbar)), "h"((uint16_t)(mask)) : "memory")
#define TCGEN05_WAIT_LD() \
    asm volatile("tcgen05.wait::ld.sync.aligned;" ::: "memory")
#define TCGEN05_FENCE_AFTER() \
    asm volatile("tcgen05.fence::after_thread_sync;" ::: "memory")

#define TCGEN05_LD_32X32B_X32(r, tmem_addr) \
    asm volatile( \
        "tcgen05.ld.sync.aligned.32x32b.x32.b32 " \
        "{%0, %1, %2, %3, %4, %5, %6, %7, " \
        " %8, %9, %10, %11, %12, %13, %14, %15, " \
        " %16, %17, %18, %19, %20, %21, %22, %23, " \
        " %24, %25, %26, %27, %28, %29, %30, %31}, [%32];" \
        : "=r"((r)[0]),  "=r"((r)[1]),  "=r"((r)[2]),  "=r"((r)[3]), \
          "=r"((r)[4]),  "=r"((r)[5]),  "=r"((r)[6]),  "=r"((r)[7]), \
          "=r"((r)[8]),  "=r"((r)[9]),  "=r"((r)[10]), "=r"((r)[11]), \
          "=r"((r)[12]), "=r"((r)[13]), "=r"((r)[14]), "=r"((r)[15]), \
          "=r"((r)[16]), "=r"((r)[17]), "=r"((r)[18]), "=r"((r)[19]), \
          "=r"((r)[20]), "=r"((r)[21]), "=r"((r)[22]), "=r"((r)[23]), \
          "=r"((r)[24]), "=r"((r)[25]), "=r"((r)[26]), "=r"((r)[27]), \
          "=r"((r)[28]), "=r"((r)[29]), "=r"((r)[30]), "=r"((r)[31]) \
        : "r"(tmem_addr))

// SW128 K-major SMEM descriptor (matches working bf16 examples)
static constexpr uint64_t SMEM_DESC_BASE_SW128 =
    (uint64_t(2) << 61) | (uint64_t(1) << 46) | (uint64_t(64) << 32) | (uint64_t(1) << 16);
#define MAKE_SMEM_DESC(base_addr) \
    (SMEM_DESC_BASE_SW128 | ((uint64_t)((base_addr) >> 4) & 0x3FFF))

#if HAS_TC
// cg2 bf16 SS MMA (from test_2cta_mma_bf16.cu)
__device__ __forceinline__ void mma_bf16_ss_cg2(uint32_t d_tmem, uint64_t a_desc,
                                                uint64_t b_desc, uint32_t idesc,
                                                uint32_t en) {
    asm volatile(
        "{\n\t"
        ".reg .pred p;\n\t"
        "setp.ne.u32 p, %5, 0;\n\t"
        "tcgen05.mma.cta_group::2.kind::f16 [%0], %1, %2, %3, "
        "{%4, %4, %4, %4, %4, %4, %4, %4}, p;\n\t"
        "}"
        :: "r"(d_tmem), "l"(a_desc), "l"(b_desc), "r"(idesc), "r"(0u), "r"(en)
        : "memory");
}
#endif

// idesc kind::f16 cg2: dtype=F32, a/b=BF16, N=256 -> 32<<17, M=256 -> 16<<24
static constexpr uint32_t IDESC_CG2 =
    (1u << 4) | (1u << 7) | (1u << 10) | (32u << 17) | (16u << 24);

// ============================================================================
// Kernel 0a: probe weight delivery format
// ============================================================================
__global__ void wprobe_kernel(const int* __restrict__ W32) {
    __shared__ int ok;
    if (threadIdx.x == 0) ok = 1;
    __syncthreads();
    for (int i = threadIdx.x; i < 8192; i += 256) {
        int v = W32[i];
        if (v < -128 || v > 127) ok = 0;
    }
    __syncthreads();
    if (threadIdx.x == 0) g_wfmt = ok;
}

// ============================================================================
// Kernel 0b: repack weights + per-channel row sums.
// tc path: bf16 into SW128 panels [o>>7][kt][16KB]. fb path: linear int8.
// ============================================================================
__global__ void __launch_bounds__(256) wrepack_kernel(const void* __restrict__ Wraw) {
    const int o = blockIdx.x;
    int s = 0;
#pragma unroll
    for (int k = 0; k < 4; k++) {
        const int i = threadIdx.x + k * 256;   // group of 4 weights
        int w0, w1, w2, w3;
        if (g_wfmt) {
            int4 v = ((const int4*)((const int*)Wraw + (size_t)o * INF))[i];
            w0 = v.x; w1 = v.y; w2 = v.z; w3 = v.w;
        } else {
            int v = ((const int*)((const int8_t*)Wraw + (size_t)o * INF))[i];
            w0 = (int)(int8_t)(v);       w1 = (int)(int8_t)(v >> 8);
            w2 = (int)(int8_t)(v >> 16); w3 = (int)(int8_t)(v >> 24);
        }
        s += w0 + w1 + w2 + w3;
#if HAS_TC
        __nv_bfloat162 h0, h1;
        h0.x = __float2bfloat16_rn((float)w0); h0.y = __float2bfloat16_rn((float)w1);
        h1.x = __float2bfloat16_rn((float)w2); h1.y = __float2bfloat16_rn((float)w3);
        const int e = i * 4;                    // element index within row
        const int kt = e >> 6, r = o & 127;
        const uint32_t boff = (uint32_t)(r * 128 + (e & 63) * 2);
        char* dst = (char*)g_Wqh + ((size_t)((o >> 7) * TCKT + kt)) * PANEL
                    + SWZ128(boff);
        *(uint2*)dst = make_uint2(*(uint32_t*)&h0, *(uint32_t*)&h1);
#else
        unsigned packed = (w0 & 0xff) | ((w1 & 0xff) << 8) |
                          ((w2 & 0xff) << 16) | ((unsigned)(w3 & 0xff) << 24);
        ((unsigned*)(g_Wq + (size_t)o * INF))[i] = packed;
#endif
    }
#pragma unroll
    for (int off = 16; off; off >>= 1) s += __shfl_xor_sync(0xffffffffu, s, off);
    __shared__ int ss[8];
    if ((threadIdx.x & 31) == 0) ss[threadIdx.x >> 5] = s;
    __syncthreads();
    if (threadIdx.x == 0) {
        int tot = 0;
#pragma unroll
        for (int i = 0; i < 8; i++) tot += ss[i];
        g_wsum[o] = tot;
    }
}

// ============================================================================
// Kernel 1: per-token dynamic asymmetric int8 quant (torchao recipe)
// tc path writes bf16 SW128 panels [t>>7][kt][16KB].
// ============================================================================
__global__ void __launch_bounds__(256) quant_kernel(const float* __restrict__ x) {
    const int t = blockIdx.x;
    const float4* xr = (const float4*)(x + (size_t)t * INF);

    float4 v[4];
    float mn = 1e38f, mx = -1e38f;
#pragma unroll
    for (int k = 0; k < 4; k++) {
        v[k] = xr[threadIdx.x + k * 256];
        mn = fminf(mn, fminf(fminf(v[k].x, v[k].y), fminf(v[k].z, v[k].w)));
        mx = fmaxf(mx, fmaxf(fmaxf(v[k].x, v[k].y), fmaxf(v[k].z, v[k].w)));
    }
#pragma unroll
    for (int o = 16; o; o >>= 1) {
        mn = fminf(mn, __shfl_xor_sync(0xffffffffu, mn, o));
        mx = fmaxf(mx, __shfl_xor_sync(0xffffffffu, mx, o));
    }

    __shared__ float smn[8], smx[8], sparams[3];
    __shared__ int sqsum;
    const int wid = threadIdx.x >> 5, lid = threadIdx.x & 31;
    if (lid == 0) { smn[wid] = mn; smx[wid] = mx; }
    if (threadIdx.x == 0) sqsum = 0;
    __syncthreads();

    if (threadIdx.x == 0) {
        float rmn = smn[0], rmx = smx[0];
#pragma unroll
        for (int i = 1; i < 8; i++) { rmn = fminf(rmn, smn[i]); rmx = fmaxf(rmx, smx[i]); }
        float min_neg = fminf(rmn, 0.0f);
        float max_pos = fmaxf(rmx, 0.0f);
        float scale = __fdiv_rn(max_pos - min_neg, 255.0f);
        scale = fmaxf(scale, 1.1920928955078125e-07f);
        float dmin = __fdiv_rn(min_neg, scale);
        float dmax = __fdiv_rn(max_pos, scale);
        float zpf = (((-128.0f + dmin) + (127.0f + dmax)) > 0.0f)
                        ? (-128.0f - dmin) : (127.0f - dmax);
        zpf = fminf(fmaxf(rintf(zpf), -128.0f), 127.0f);
        sparams[0] = scale;
        sparams[1] = zpf;
        sparams[2] = __frcp_rn(scale);
    }
    __syncthreads();

    const float scale = sparams[0], zp = sparams[1], rcp = sparams[2];
    int qsum = 0;
#pragma unroll
    for (int k = 0; k < 4; k++) {
        float e4[4] = {v[k].x, v[k].y, v[k].z, v[k].w};
        int q[4];
#pragma unroll
        for (int j = 0; j < 4; j++) {
            float y0 = __fmul_rn(e4[j], rcp);
            float y = fmaf(fmaf(-scale, y0, e4[j]), rcp, y0);  // IEEE-div accurate
            float qf = fminf(fmaxf(rintf(y) + zp, -128.0f), 127.0f);
            q[j] = (int)qf;
            qsum += q[j];
        }
        const int i = threadIdx.x + k * 256;
#if HAS_TC
        __nv_bfloat162 h0, h1;
        h0.x = __float2bfloat16_rn((float)q[0]); h0.y = __float2bfloat16_rn((float)q[1]);
        h1.x = __float2bfloat16_rn((float)q[2]); h1.y = __float2bfloat16_rn((float)q[3]);
        const int e = i * 4;
        const int kt = e >> 6, r = t & 127;
        const uint32_t boff = (uint32_t)(r * 128 + (e & 63) * 2);
        char* dst = (char*)g_Aqh + ((size_t)((t >> 7) * TCKT + kt)) * PANEL
                    + SWZ128(boff);
        *(uint2*)dst = make_uint2(*(uint32_t*)&h0, *(uint32_t*)&h1);
#else
        unsigned packed = (q[0] & 0xff) | ((q[1] & 0xff) << 8) |
                          ((q[2] & 0xff) << 16) | ((unsigned)(q[3] & 0xff) << 24);
        ((int*)g_Aq)[(size_t)t * (INF / 4) + i] = (int)packed;
#endif
    }

#pragma unroll
    for (int o = 16; o; o >>= 1) qsum += __shfl_xor_sync(0xffffffffu, qsum, o);
    if (lid == 0) atomicAdd(&sqsum, qsum);
    __syncthreads();
    if (threadIdx.x == 0) {
        g_ascale[t] = scale;
        g_azp[t]    = zp;
        g_aqsum[t]  = sqsum;
    }
}

// ============================================================================
// Kernel 2a: cg2 tcgen05 bf16 GEMM, pair = 256x256, 2 CTAs per SM.
// 3-stage mod-3 ring (lead-2), all-thread LDGSTS, TMEM 256 cols per CTA.
// ============================================================================
__global__ void __launch_bounds__(128, 2) __cluster_dims__(2, 1, 1)
gemm_tc(float* __restrict__ out,
        const float* __restrict__ scales, const float* __restrict__ zeros,
        int OUTF) {
#if HAS_TC
    extern __shared__ char smem[];
    const uint32_t sb = smem_to_u32(smem);
    const int tid = threadIdx.x;
    const int wid = tid >> 5;
    uint32_t rank;
    asm("mov.u32 %0, %%cluster_ctarank;" : "=r"(rank));
    const int m0 = blockIdx.x * 128;          // this CTA's 128 token rows
    const int n0 = blockIdx.y * 256;          // pair's 256 output channels

    if (wid == 0) TCGEN05_ALLOC_CG2(sb, 256);
    if (tid == 0) {
#pragma unroll
        for (int s = 0; s < TCSTAGES; s++) {
            MBARRIER_INIT(sb + MB_FULL(s), 2);
            MBARRIER_INIT(sb + MB_EMPTY(s), 1);
        }
        MBARRIER_INIT(sb + MB_DONE, 1);
    }
    __syncthreads();
    uint32_t tmem;
    asm volatile("ld.shared.b32 %0, [%1];" : "=r"(tmem) : "r"(sb));
    if (wid == 0) TCGEN05_RELINQUISH_CG2();
    CLUSTER_SYNC();   // mbarriers visible cluster-wide before any remote arrive

    // panel bases (generic pointers; cp.async converts)
    const char* Ap = (const char*)g_Aqh + (size_t)blockIdx.x * TCKT * PANEL;
    const char* Bp = (const char*)g_Wqh +
                     (size_t)(blockIdx.y * 2 + rank) * TCKT * PANEL;

    // all 128 threads load a stage (A 16KB + B 16KB), linear pre-swizzled copy
    auto load_stage = [&](int s, int kt) {
        const uint32_t dst = sb + TC_STG(s);
        const char* a = Ap + (size_t)kt * PANEL;
        const char* b = Bp + (size_t)kt * PANEL;
#pragma unroll
        for (int i = 0; i < 8; i++) {
            const uint32_t o = (uint32_t)(i * 128 + tid) * 16;
            CP_ASYNC16(dst + o, a + o);
        }
#pragma unroll
        for (int i = 0; i < 8; i++) {
            const uint32_t o = (uint32_t)(i * 128 + tid) * 16;
            CP_ASYNC16(dst + PANEL + o, b + o);
        }
    };

    // prologue: stages 0,1 (lead = 2)
    load_stage(0, 0); CP_COMMIT();
    load_stage(1, 1); CP_COMMIT();

    for (int kt = 0; kt < TCKT; kt++) {
        const int s = kt % 3;
        CP_WAIT(1);          // load(kt) complete (this thread's groups)
        __syncthreads();     // all threads' chunks landed

        if (tid == 0) {
            FENCE_PROXY_ASYNC();                       // generic -> async proxy
            MBARRIER_ARRIVE_CLUSTER(sb + MB_FULL(s), 0);  // to pair leader
            if (rank == 0) {
                MBARRIER_WAIT_PARITY_CLUS(sb + MB_FULL(s), (kt / 3) & 1);
                const uint64_t ad = MAKE_SMEM_DESC(sb + TC_STG(s));
                const uint64_t bd = MAKE_SMEM_DESC(sb + TC_STG(s) + PANEL);
#pragma unroll
                for (int j = 0; j < 4; j++)   // 4 x K=16 per 64-elem ktile
                    mma_bf16_ss_cg2(tmem, ad + j * 2, bd + j * 2, IDESC_CG2,
                                    (uint32_t)((kt | j) != 0));
                TCGEN05_COMMIT_MC_CG2(sb + MB_EMPTY(s), 0x3);
            }
        }

        const int nk = kt + 2;               // reload stage (kt+2)%3
        if (nk < TCKT) {
            if (kt >= 1) {
                // stage (kt+2)%3 == (kt-1)%3 was last read by MMA(kt-1)
                MBARRIER_WAIT_PARITY(sb + MB_EMPTY((kt - 1) % 3),
                                     ((kt - 1) / 3) & 1);
            }
            load_stage(nk % 3, nk);
        }
        CP_COMMIT();   // always commit so wait_group count stays exact
    }

    if (tid == 0 && rank == 0)
        TCGEN05_COMMIT_MC_CG2(sb + MB_DONE, 0x3);  // single-flip completion

    MBARRIER_WAIT_PARITY_CLUS(sb + MB_DONE, 0);
    TCGEN05_FENCE_AFTER();

    // ---- epilogue: dequant f32 accumulators; smem transpose for coalesced IO
    const int t = m0 + tid;   // warp w owns TMEM lanes 32w..32w+31 -> row m0+tid
    const float s_t = g_ascale[t];
    const float zp  = g_azp[t];
    const float ct  = (float)g_aqsum[t] - (float)INF * zp;
    float* xp = (float*)(smem + 1024);   // 128 rows x 68 floats (reuses stages)

#pragma unroll
    for (int ch = 0; ch < 4; ch++) {
        uint32_t r[64];
        TCGEN05_LD_32X32B_X32(r, tmem + ch * 64);
        TCGEN05_LD_32X32B_X32(r + 32, tmem + ch * 64 + 32);
        TCGEN05_WAIT_LD();
        const int cb = n0 + ch * 64;
        __syncthreads();
#pragma unroll
        for (int c = 0; c < 64; c += 4) {
            float4 v;
            v.x = s_t * __ldg(scales + cb + c + 0) *
                  (__uint_as_float(r[c + 0]) - zp * (float)g_wsum[cb + c + 0] - __ldg(zeros + cb + c + 0) * ct);
            v.y = s_t * __ldg(scales + cb + c + 1) *
                  (__uint_as_float(r[c + 1]) - zp * (float)g_wsum[cb + c + 1] - __ldg(zeros + cb + c + 1) * ct);
            v.z = s_t * __ldg(scales + cb + c + 2) *
                  (__uint_as_float(r[c + 2]) - zp * (float)g_wsum[cb + c + 2] - __ldg(zeros + cb + c + 2) * ct);
            v.w = s_t * __ldg(scales + cb + c + 3) *
                  (__uint_as_float(r[c + 3]) - zp * (float)g_wsum[cb + c + 3] - __ldg(zeros + cb + c + 3) * ct);
            *(float4*)(xp + tid * 68 + c) = v;
        }
        __syncthreads();
#pragma unroll
        for (int it = 0; it < 16; it++) {
            int idx = it * 128 + tid;
            int row = idx >> 4, q = idx & 15;
            float4 v = *(const float4*)(xp + row * 68 + q * 4);
            *(float4*)(out + (size_t)(m0 + row) * OUTF + cb + q * 4) = v;
        }
    }

    __syncthreads();
    CLUSTER_SYNC();
    if (wid == 0) TCGEN05_DEALLOC_CG2(tmem, 256);
    CLUSTER_SYNC();
#endif  // HAS_TC
}

// ============================================================================
// Kernel 2b: fallback mma.sync s8 GEMM — non-'a' pass only
// ============================================================================
__global__ void __launch_bounds__(256, 2)
gemm_fb(float* __restrict__ out,
        const float* __restrict__ scales, const float* __restrict__ zeros,
        int OUTF) {
#if !HAS_TC
    extern __shared__ char smem[];
    const uint32_t sb = smem_to_u32(smem);
    const int tid  = threadIdx.x;
    const int lane = tid & 31;
    const int wid  = tid >> 5;
    const int warp_m = wid & 1;
    const int warp_n = wid >> 1;
    const int m0 = blockIdx.x * BM;
    const int n0 = blockIdx.y * BN;

    const int8_t* Abase = g_Aq + (size_t)m0 * INF;
    const int8_t* Bbase = g_Wq + (size_t)n0 * INF;

    auto load_stage = [&](int s, int kt) {
        const uint32_t st = sb + s * STAGE_BYTES;
        const int8_t* ga = Abase + kt * BK;
        const int8_t* gb = Bbase + kt * BK;
#pragma unroll
        for (int i = 0; i < 2; i++) {
            int idx = i * 256 + tid;
            int row = idx >> 2, ch = idx & 3;
            CP_ASYNC16(st + row * 64 + SWZ_CHUNK(row, ch) * 16,
                       ga + (size_t)row * INF + ch * 16);
        }
#pragma unroll
        for (int i = 0; i < 2; i++) {
            int idx = i * 256 + tid;
            int row = idx >> 2, ch = idx & 3;
            CP_ASYNC16(st + BM * BK + row * 64 + SWZ_CHUNK(row, ch) * 16,
                       gb + (size_t)row * INF + ch * 16);
        }
    };

    int acc[4][4][4];
#pragma unroll
    for (int i = 0; i < 4; i++)
#pragma unroll
        for (int j = 0; j < 4; j++)
#pragma unroll
            for (int k = 0; k < 4; k++) acc[i][j][k] = 0;

    const uint32_t key = ((lane & 15) >> 1) & 3;
    const int hi = lane >> 4;
    const uint32_t a_row = (uint32_t)(warp_m * 64 + (lane & 15)) * 64;
    const uint32_t b_row = (uint32_t)(warp_n * 32 + (lane & 15)) * 64;

#pragma unroll
    for (int s = 0; s < STAGES - 1; s++) { load_stage(s, s); CP_COMMIT(); }

    for (int kt = 0; kt < KTILES; kt++) {
        const int ns = kt + STAGES - 1;
        if (ns < KTILES) load_stage(ns & (STAGES - 1), ns);
        CP_COMMIT();
        CP_WAIT(STAGES - 1);
        __syncthreads();

        const uint32_t sA = sb + (kt & (STAGES - 1)) * STAGE_BYTES;
        const uint32_t sB = sA + BM * BK;
#pragma unroll
        for (int ks = 0; ks < 2; ks++) {
            const uint32_t choff = (uint32_t)(((ks << 1) | hi) ^ key) << 4;
            uint32_t a[4][4];
#pragma unroll
            for (int mf = 0; mf < 4; mf++)
                ldmatrix_x4(a[mf][0], a[mf][1], a[mf][2], a[mf][3],
                            sA + a_row + mf * 1024 + choff);
            uint32_t b0[4], b1[4];
#pragma unroll
            for (int p = 0; p < 2; p++)
                ldmatrix_x4(b0[2 * p], b0[2 * p + 1], b1[2 * p], b1[2 * p + 1],
                            sB + b_row + p * 1024 + choff);
#pragma unroll
            for (int mf = 0; mf < 4; mf++)
#pragma unroll
                for (int nf = 0; nf < 4; nf++)
                    mma_s8(acc[mf][nf], a[mf], b0[nf], b1[nf]);
        }
        __syncthreads();
    }

    float s_t[8], zp_t[8], ct_t[8];
#pragma unroll
    for (int mf = 0; mf < 4; mf++)
#pragma unroll
        for (int h = 0; h < 2; h++) {
            int r = m0 + warp_m * 64 + mf * 16 + (lane >> 2) + 8 * h;
            float s = g_ascale[r], z = g_azp[r];
            s_t[mf * 2 + h] = s;
            zp_t[mf * 2 + h] = z;
            ct_t[mf * 2 + h] = (float)g_aqsum[r] - (float)INF * z;
        }

#pragma unroll
    for (int nf = 0; nf < 4; nf++) {
        const int c0 = n0 + warp_n * 32 + nf * 8 + (lane & 3) * 2;
        const float sc0 = __ldg(scales + c0), sc1 = __ldg(scales + c0 + 1);
        const float z0  = __ldg(zeros + c0),  z1  = __ldg(zeros + c0 + 1);
        const float w0  = (float)g_wsum[c0],  w1  = (float)g_wsum[c0 + 1];
#pragma unroll
        for (int mf = 0; mf < 4; mf++)
#pragma unroll
            for (int h = 0; h < 2; h++) {
                const int r = m0 + warp_m * 64 + mf * 16 + (lane >> 2) + 8 * h;
                const float s = s_t[mf * 2 + h], zp = zp_t[mf * 2 + h],
                            ct = ct_t[mf * 2 + h];
                float2 v;
                v.x = s * sc0 * ((float)acc[mf][nf][h * 2 + 0] - zp * w0 - z0 * ct);
                v.y = s * sc1 * ((float)acc[mf][nf][h * 2 + 1] - zp * w1 - z1 * ct);
                *(float2*)(out + (size_t)r * OUTF + c0) = v;
            }
    }
#endif  // !HAS_TC
}

// ============================================================================
// Launcher — both GEMMs launched; exactly one is non-empty in the loaded SASS.
// ============================================================================
extern "C" void kernel_launch(void* const* d_in, const int* in_sizes, int n_in,
                              void* d_out, int out_size) {
    (void)n_in; (void)out_size;
    const float* x      = (const float*)d_in[0];
    const void*  w      = d_in[1];
    const float* scales = (const float*)d_in[2];
    const float* zeros  = (const float*)d_in[3];
    float* out = (float*)d_out;

    const int tokens = in_sizes[0] / INF;
    const int outf   = in_sizes[2];

    wprobe_kernel<<<1, 256>>>((const int*)w);
    wrepack_kernel<<<outf, 256>>>(w);
    quant_kernel<<<tokens, 256>>>(x);

    cudaFuncSetAttribute(gemm_tc,
                         cudaFuncAttributeMaxDynamicSharedMemorySize, TC_SMEM);
    cudaFuncSetAttribute(gemm_fb,
                         cudaFuncAttributeMaxDynamicSharedMemorySize, SMEM_TOTAL);

    // tc grid: x = 64 m-subtiles (cluster pairs adjacent x), y = 43 n-tiles
    gemm_tc<<<dim3(tokens / 128, outf / 256), 128, TC_SMEM>>>(
        out, scales, zeros, outf);
    gemm_fb<<<dim3(tokens / BM, outf / BN), 256, SMEM_TOTAL>>>(
        out, scales, zeros, outf);
}